// round 11
// baseline (speedup 1.0000x reference)
#include <cuda_runtime.h>

#define N_NODES 100000
#define N_EDGES 1600000
#define F_IN    128
#define F_HID   64
#define F_OUT   47
#define F_OUT_P 48   // padded

#define NBLK_N  391          // ceil(100000/256)

// ---------------- scratch (allocation-guard compliant) ----------------
__device__ __align__(16) float g_y1[N_NODES * F_HID];    // (x@W1)*dinv[row]
__device__ __align__(16) float g_y2[N_NODES * F_OUT_P];  // (h@W2)*dinv[row]
__device__ float g_dinv  [N_NODES];
__device__ int   g_cnt   [N_NODES];
__device__ int   g_start [N_NODES];
__device__ int   g_cursor[N_NODES];
__device__ int   g_alloc;                                // edge-chunk bump allocator
__device__ int   g_col[N_EDGES];                         // CSR column (src) list

// ---------------- CSR build ----------------
__global__ void k_cnt(const int* __restrict__ dst) {
    int e = blockIdx.x * 256 + threadIdx.x;
    if (e < N_EDGES) atomicAdd(&g_cnt[dst[e]], 1);
}

// fused scan: block-local exclusive scan + atomic chunk grab.
__global__ void k_scanfix() {
    __shared__ int sh[256];
    __shared__ int base_sh;
    int t = threadIdx.x;
    int i = blockIdx.x * 256 + t;
    int v = (i < N_NODES) ? g_cnt[i] : 0;
    sh[t] = v;
    __syncthreads();
#pragma unroll
    for (int off = 1; off < 256; off <<= 1) {
        int u = (t >= off) ? sh[t - off] : 0;
        __syncthreads();
        sh[t] += u;
        __syncthreads();
    }
    if (t == 255) base_sh = atomicAdd(&g_alloc, sh[255]);
    __syncthreads();
    if (i < N_NODES) {
        int start = base_sh + sh[t] - v;
        g_start[i]  = start;
        g_cursor[i] = start;
        g_dinv[i]   = rsqrtf((float)(v + 1));    // deg = cnt + 1 (self-loop)
    }
}

__global__ void k_fill(const int* __restrict__ src, const int* __restrict__ dst) {
    int e = blockIdx.x * 256 + threadIdx.x;
    if (e < N_EDGES) {
        int pos = atomicAdd(&g_cursor[dst[e]], 1);
        g_col[pos] = src[e];
    }
}

// ---------------- GEMM1 v2: register-blocked 64x64 tile, 4x4 per thread ----------
// y1[N,64] = (x[N,128] @ W1) * dinv[row].  K streamed in 4 chunks of 32.
// Per k4 step: 8 LDS.128 feed 64 FFMA (ratio 8:1) -> FMA-pipe bound.
__global__ void k_gemm1(const float* __restrict__ x, const float* __restrict__ W1) {
    __shared__ float4 xs4[64][8];             // 64 rows x 32 k  (8 KB)
    __shared__ float4 ws4[32][16];            // 32 k x 64 cols  (8 KB)
    int t  = threadIdx.x;
    int tx = t & 15;                          // col group: cols tx*4 .. tx*4+3
    int ty = t >> 4;                          // row group: rows ty*4 .. ty*4+3
    int row0 = blockIdx.x * 64;

    float4 acc0 = make_float4(0.f, 0.f, 0.f, 0.f);
    float4 acc1 = make_float4(0.f, 0.f, 0.f, 0.f);
    float4 acc2 = make_float4(0.f, 0.f, 0.f, 0.f);
    float4 acc3 = make_float4(0.f, 0.f, 0.f, 0.f);

    const float4* xg = (const float4*)x;      // x rows: 32 float4 each
    const float4* wg = (const float4*)W1;     // W1 rows: 16 float4 each

#pragma unroll
    for (int kc = 0; kc < 4; ++kc) {
        // load x chunk: 64 rows x 8 float4
        for (int i = t; i < 512; i += 256) {
            int row = i >> 3, k4 = i & 7;
            float4 v = make_float4(0.f, 0.f, 0.f, 0.f);
            if (row0 + row < N_NODES)
                v = xg[(size_t)(row0 + row) * 32 + kc * 8 + k4];
            xs4[row][k4] = v;
        }
        // load W chunk: 32 k x 16 float4 (contiguous rows of W1)
        for (int i = t; i < 512; i += 256) {
            int k = i >> 4, c4 = i & 15;
            ws4[k][c4] = wg[(size_t)(kc * 32 + k) * 16 + c4];
        }
        __syncthreads();

#pragma unroll
        for (int k4 = 0; k4 < 8; ++k4) {
            float4 a0 = xs4[ty * 4 + 0][k4];
            float4 a1 = xs4[ty * 4 + 1][k4];
            float4 a2 = xs4[ty * 4 + 2][k4];
            float4 a3 = xs4[ty * 4 + 3][k4];
            float4 w0 = ws4[k4 * 4 + 0][tx];
            float4 w1 = ws4[k4 * 4 + 1][tx];
            float4 w2 = ws4[k4 * 4 + 2][tx];
            float4 w3 = ws4[k4 * 4 + 3][tx];

            acc0.x += a0.x*w0.x; acc0.x += a0.y*w1.x; acc0.x += a0.z*w2.x; acc0.x += a0.w*w3.x;
            acc0.y += a0.x*w0.y; acc0.y += a0.y*w1.y; acc0.y += a0.z*w2.y; acc0.y += a0.w*w3.y;
            acc0.z += a0.x*w0.z; acc0.z += a0.y*w1.z; acc0.z += a0.z*w2.z; acc0.z += a0.w*w3.z;
            acc0.w += a0.x*w0.w; acc0.w += a0.y*w1.w; acc0.w += a0.z*w2.w; acc0.w += a0.w*w3.w;

            acc1.x += a1.x*w0.x; acc1.x += a1.y*w1.x; acc1.x += a1.z*w2.x; acc1.x += a1.w*w3.x;
            acc1.y += a1.x*w0.y; acc1.y += a1.y*w1.y; acc1.y += a1.z*w2.y; acc1.y += a1.w*w3.y;
            acc1.z += a1.x*w0.z; acc1.z += a1.y*w1.z; acc1.z += a1.z*w2.z; acc1.z += a1.w*w3.z;
            acc1.w += a1.x*w0.w; acc1.w += a1.y*w1.w; acc1.w += a1.z*w2.w; acc1.w += a1.w*w3.w;

            acc2.x += a2.x*w0.x; acc2.x += a2.y*w1.x; acc2.x += a2.z*w2.x; acc2.x += a2.w*w3.x;
            acc2.y += a2.x*w0.y; acc2.y += a2.y*w1.y; acc2.y += a2.z*w2.y; acc2.y += a2.w*w3.y;
            acc2.z += a2.x*w0.z; acc2.z += a2.y*w1.z; acc2.z += a2.z*w2.z; acc2.z += a2.w*w3.z;
            acc2.w += a2.x*w0.w; acc2.w += a2.y*w1.w; acc2.w += a2.z*w2.w; acc2.w += a2.w*w3.w;

            acc3.x += a3.x*w0.x; acc3.x += a3.y*w1.x; acc3.x += a3.z*w2.x; acc3.x += a3.w*w3.x;
            acc3.y += a3.x*w0.y; acc3.y += a3.y*w1.y; acc3.y += a3.z*w2.y; acc3.y += a3.w*w3.y;
            acc3.z += a3.x*w0.z; acc3.z += a3.y*w1.z; acc3.z += a3.z*w2.z; acc3.z += a3.w*w3.z;
            acc3.w += a3.x*w0.w; acc3.w += a3.y*w1.w; acc3.w += a3.z*w2.w; acc3.w += a3.w*w3.w;
        }
        __syncthreads();
    }

    // epilogue: scale by dinv[row], vector store
    int r = row0 + ty * 4;
    float4* yo = (float4*)g_y1;
    if (r + 0 < N_NODES) {
        float d = g_dinv[r + 0];
        acc0.x *= d; acc0.y *= d; acc0.z *= d; acc0.w *= d;
        yo[(size_t)(r + 0) * 16 + tx] = acc0;
    }
    if (r + 1 < N_NODES) {
        float d = g_dinv[r + 1];
        acc1.x *= d; acc1.y *= d; acc1.z *= d; acc1.w *= d;
        yo[(size_t)(r + 1) * 16 + tx] = acc1;
    }
    if (r + 2 < N_NODES) {
        float d = g_dinv[r + 2];
        acc2.x *= d; acc2.y *= d; acc2.z *= d; acc2.w *= d;
        yo[(size_t)(r + 2) * 16 + tx] = acc2;
    }
    if (r + 3 < N_NODES) {
        float d = g_dinv[r + 3];
        acc3.x *= d; acc3.y *= d; acc3.z *= d; acc3.w *= d;
        yo[(size_t)(r + 3) * 16 + tx] = acc3;
    }
}

// ------- fused gather1 + GEMM2 -------
// Phase A (256 thr, 16 thr/node): h = relu( dinv·(Σ_nbr y1[nbr] + y1[d]) + b1 ) -> smem
// Phase B (192 thr): y2[16 rows, 48 cols] = (h @ W2pad) * dinv[row], written direct.
__global__ void k_g1g2(const float* __restrict__ b1, const float* __restrict__ W2) {
    __shared__ float hs[16][F_HID];           // 4 KB
    __shared__ float ws[F_HID][F_OUT_P];      // 12 KB (col 47 zero-padded)
    int t = threadIdx.x;
    for (int i = t; i < F_HID * F_OUT_P; i += 256) {
        int k = i / F_OUT_P, c = i - k * F_OUT_P;
        ws[k][c] = (c < F_OUT) ? W2[k * F_OUT + c] : 0.0f;
    }

    // ---- Phase A: gather ----
    int node = blockIdx.x * 16 + (t >> 4);
    int c = t & 15;
    const float4* y = (const float4*)g_y1;
    float di = g_dinv[node];
    float4 a0 = __ldg(&y[(size_t)node * 16 + c]);   // self term (unscaled!)
    float4 a1 = make_float4(0.f, 0.f, 0.f, 0.f);
    float4 a2 = make_float4(0.f, 0.f, 0.f, 0.f);
    float4 a3 = make_float4(0.f, 0.f, 0.f, 0.f);
    int j   = g_start[node];
    int end = j + g_cnt[node];
    for (; j + 4 <= end; j += 4) {                   // MLP=4
        int s0 = g_col[j + 0], s1 = g_col[j + 1];
        int s2 = g_col[j + 2], s3 = g_col[j + 3];
        float4 v0 = __ldg(&y[(size_t)s0 * 16 + c]);
        float4 v1 = __ldg(&y[(size_t)s1 * 16 + c]);
        float4 v2 = __ldg(&y[(size_t)s2 * 16 + c]);
        float4 v3 = __ldg(&y[(size_t)s3 * 16 + c]);
        a0.x += v0.x; a0.y += v0.y; a0.z += v0.z; a0.w += v0.w;
        a1.x += v1.x; a1.y += v1.y; a1.z += v1.z; a1.w += v1.w;
        a2.x += v2.x; a2.y += v2.y; a2.z += v2.z; a2.w += v2.w;
        a3.x += v3.x; a3.y += v3.y; a3.z += v3.z; a3.w += v3.w;
    }
    for (; j < end; ++j) {
        int s = g_col[j];
        float4 v = __ldg(&y[(size_t)s * 16 + c]);
        a0.x += v.x; a0.y += v.y; a0.z += v.z; a0.w += v.w;
    }
    a0.x += a1.x + a2.x + a3.x;
    a0.y += a1.y + a2.y + a3.y;
    a0.z += a1.z + a2.z + a3.z;
    a0.w += a1.w + a2.w + a3.w;
    float4 b = ((const float4*)b1)[c];
    float4 h;
    h.x = fmaxf(fmaf(a0.x, di, b.x), 0.f);
    h.y = fmaxf(fmaf(a0.y, di, b.y), 0.f);
    h.z = fmaxf(fmaf(a0.z, di, b.z), 0.f);
    h.w = fmaxf(fmaf(a0.w, di, b.w), 0.f);
    *(float4*)&hs[t >> 4][c * 4] = h;
    __syncthreads();

    // ---- Phase B: 16x48 = h[16x64] @ ws[64x48] ----
    if (t < 192) {
        int cp = t % 24;
        int rg = t / 24;                       // 0..7
        int c0 = cp * 2;
        float acc00 = 0.f, acc01 = 0.f, acc10 = 0.f, acc11 = 0.f;
#pragma unroll 8
        for (int k = 0; k < F_HID; ++k) {
            float va = hs[rg * 2 + 0][k];
            float vb = hs[rg * 2 + 1][k];
            float w0 = ws[k][c0];
            float w1 = ws[k][c0 + 1];
            acc00 += va * w0; acc01 += va * w1;
            acc10 += vb * w0; acc11 += vb * w1;
        }
        int r0 = blockIdx.x * 16 + rg * 2;
        float d0 = g_dinv[r0 + 0];
        float d1 = g_dinv[r0 + 1];
        g_y2[(size_t)(r0 + 0) * F_OUT_P + c0 + 0] = acc00 * d0;
        g_y2[(size_t)(r0 + 0) * F_OUT_P + c0 + 1] = acc01 * d0;
        g_y2[(size_t)(r0 + 1) * F_OUT_P + c0 + 0] = acc10 * d1;
        g_y2[(size_t)(r0 + 1) * F_OUT_P + c0 + 1] = acc11 * d1;
    }
}

// ------- gather2 + fused log-softmax: out = logsoftmax( dinv·(Σ + y2[d]) + b2 ) -------
__global__ void k_gather2(const float* __restrict__ b2, float* __restrict__ out) {
    int t = threadIdx.x;
    int node = blockIdx.x * 16 + (t >> 4);
    int c = t & 15;
    bool act = (c < 12);
    float di = g_dinv[node];
    float4 v = make_float4(-1e30f, -1e30f, -1e30f, -1e30f);

    if (act) {
        const float4* y = (const float4*)g_y2;
        float4 a0 = __ldg(&y[(size_t)node * 12 + c]);   // self term (unscaled)
        float4 a1 = make_float4(0.f, 0.f, 0.f, 0.f);
        float4 a2 = make_float4(0.f, 0.f, 0.f, 0.f);
        float4 a3 = make_float4(0.f, 0.f, 0.f, 0.f);
        int j   = g_start[node];
        int end = j + g_cnt[node];
        for (; j + 4 <= end; j += 4) {                   // MLP=4
            int s0 = g_col[j + 0], s1 = g_col[j + 1];
            int s2 = g_col[j + 2], s3 = g_col[j + 3];
            float4 v0 = __ldg(&y[(size_t)s0 * 12 + c]);
            float4 v1 = __ldg(&y[(size_t)s1 * 12 + c]);
            float4 v2 = __ldg(&y[(size_t)s2 * 12 + c]);
            float4 v3 = __ldg(&y[(size_t)s3 * 12 + c]);
            a0.x += v0.x; a0.y += v0.y; a0.z += v0.z; a0.w += v0.w;
            a1.x += v1.x; a1.y += v1.y; a1.z += v1.z; a1.w += v1.w;
            a2.x += v2.x; a2.y += v2.y; a2.z += v2.z; a2.w += v2.w;
            a3.x += v3.x; a3.y += v3.y; a3.z += v3.z; a3.w += v3.w;
        }
        for (; j < end; ++j) {
            int s = g_col[j];
            float4 w = __ldg(&y[(size_t)s * 12 + c]);
            a0.x += w.x; a0.y += w.y; a0.z += w.z; a0.w += w.w;
        }
        a0.x += a1.x + a2.x + a3.x;
        a0.y += a1.y + a2.y + a3.y;
        a0.z += a1.z + a2.z + a3.z;
        a0.w += a1.w + a2.w + a3.w;

        float bx, by, bz, bw;
        if (c < 11) {
            bx = b2[c * 4 + 0]; by = b2[c * 4 + 1];
            bz = b2[c * 4 + 2]; bw = b2[c * 4 + 3];
        } else {
            bx = b2[44]; by = b2[45]; bz = b2[46]; bw = 0.f;
        }
        v.x = fmaf(a0.x, di, bx);
        v.y = fmaf(a0.y, di, by);
        v.z = fmaf(a0.z, di, bz);
        v.w = (c < 11) ? fmaf(a0.w, di, bw) : -1e30f;   // col 47 is padding
    }

    float m = fmaxf(fmaxf(v.x, v.y), fmaxf(v.z, v.w));
#pragma unroll
    for (int off = 1; off < 16; off <<= 1)
        m = fmaxf(m, __shfl_xor_sync(0xffffffffu, m, off, 16));

    float s = act ? (expf(v.x - m) + expf(v.y - m) + expf(v.z - m) + expf(v.w - m))
                  : 0.f;
#pragma unroll
    for (int off = 1; off < 16; off <<= 1)
        s += __shfl_xor_sync(0xffffffffu, s, off, 16);

    float ls = m + logf(s);
    if (act) {
        size_t base = (size_t)node * F_OUT + c * 4;
        out[base + 0] = v.x - ls;
        out[base + 1] = v.y - ls;
        out[base + 2] = v.z - ls;
        if (c < 11) out[base + 3] = v.w - ls;
    }
}

// ---------------- launch (6 kernels + 2 memset nodes, graph-capturable) ----------------
extern "C" void kernel_launch(void* const* d_in, const int* in_sizes, int n_in,
                              void* d_out, int out_size) {
    const float* x  = (const float*)d_in[0];
    const int*   ei = (const int*)  d_in[1];
    const float* W1 = (const float*)d_in[2];
    const float* b1 = (const float*)d_in[3];
    const float* W2 = (const float*)d_in[4];
    const float* b2 = (const float*)d_in[5];
    float* out = (float*)d_out;
    const int* src = ei;
    const int* dst = ei + N_EDGES;

    void *p_cnt = nullptr, *p_alloc = nullptr;
    cudaGetSymbolAddress(&p_cnt,   g_cnt);
    cudaGetSymbolAddress(&p_alloc, g_alloc);
    cudaMemsetAsync(p_cnt,   0, N_NODES * sizeof(int));
    cudaMemsetAsync(p_alloc, 0, sizeof(int));

    // CSR build
    k_cnt     <<<(N_EDGES + 255) / 256, 256>>>(dst);
    k_scanfix <<<NBLK_N, 256>>>();
    k_fill    <<<(N_EDGES + 255) / 256, 256>>>(src, dst);

    // layer 1 GEMM (register-blocked), fused gather1+GEMM2, fused gather2+softmax
    k_gemm1   <<<(N_NODES + 63) / 64, 256>>>(x, W1);
    k_g1g2    <<<N_NODES / 16, 256>>>(b1, W2);
    k_gather2 <<<N_NODES / 16, 256>>>(b2, out);
}

// round 12
// speedup vs baseline: 1.4341x; 1.4341x over previous
#include <cuda_runtime.h>

#define N_NODES 100000
#define N_EDGES 1600000
#define F_IN    128
#define F_HID   64
#define F_OUT   47
#define F_OUT_P 48   // padded

#define NBLK_N  391          // ceil(100000/256)

// ---------------- scratch (allocation-guard compliant) ----------------
__device__ __align__(16) float g_y1[N_NODES * F_HID];    // (x@W1)*dinv[row]
__device__ __align__(16) float g_y2[N_NODES * F_OUT_P];  // (h@W2)*dinv[row]
__device__ float g_dinv  [N_NODES];
__device__ int   g_cnt   [N_NODES];
__device__ int   g_start [N_NODES];
__device__ int   g_cursor[N_NODES];
__device__ int   g_alloc;                                // edge-chunk bump allocator
__device__ int   g_col[N_EDGES];                         // CSR column (src) list

// ---- sm_103a packed fp32 helpers (FFMA2 path; IEEE fp32 per lane) ----
__device__ __forceinline__ unsigned long long pk2(float lo, float hi) {
    unsigned long long r;
    asm("mov.b64 %0, {%1,%2};" : "=l"(r) : "f"(lo), "f"(hi));
    return r;
}
__device__ __forceinline__ void fma2(unsigned long long& d,
                                     unsigned long long a, unsigned long long b) {
    asm("fma.rn.f32x2 %0, %1, %2, %0;" : "+l"(d) : "l"(a), "l"(b));
}
__device__ __forceinline__ void upk2(unsigned long long v, float& lo, float& hi) {
    asm("mov.b64 {%0,%1}, %2;" : "=f"(lo), "=f"(hi) : "l"(v));
}

// ---------------- CSR build ----------------
__global__ void k_cnt(const int* __restrict__ dst) {
    int e = blockIdx.x * 256 + threadIdx.x;
    if (e < N_EDGES) atomicAdd(&g_cnt[dst[e]], 1);
}

// fused scan: block-local exclusive scan + atomic chunk grab.
__global__ void k_scanfix() {
    __shared__ int sh[256];
    __shared__ int base_sh;
    int t = threadIdx.x;
    int i = blockIdx.x * 256 + t;
    int v = (i < N_NODES) ? g_cnt[i] : 0;
    sh[t] = v;
    __syncthreads();
#pragma unroll
    for (int off = 1; off < 256; off <<= 1) {
        int u = (t >= off) ? sh[t - off] : 0;
        __syncthreads();
        sh[t] += u;
        __syncthreads();
    }
    if (t == 255) base_sh = atomicAdd(&g_alloc, sh[255]);
    __syncthreads();
    if (i < N_NODES) {
        int start = base_sh + sh[t] - v;
        g_start[i]  = start;
        g_cursor[i] = start;
        g_dinv[i]   = rsqrtf((float)(v + 1));    // deg = cnt + 1 (self-loop)
    }
}

__global__ void k_fill(const int* __restrict__ src, const int* __restrict__ dst) {
    int e = blockIdx.x * 256 + threadIdx.x;
    if (e < N_EDGES) {
        int pos = atomicAdd(&g_cursor[dst[e]], 1);
        g_col[pos] = src[e];
    }
}

// ---------------- GEMM1 v3: 64x64 tile, 4x4/thread, packed FFMA2 ----------------
// y1[N,64] = (x[N,128] @ W1) * dinv[row].  K streamed in 4 chunks of 32.
// Inner product uses fma.rn.f32x2: 2 FMAs/issue -> halves the FFMA-issue floor.
__global__ void k_gemm1(const float* __restrict__ x, const float* __restrict__ W1) {
    __shared__ float4 xs4[64][8];             // 64 rows x 32 k  (8 KB)
    __shared__ float4 ws4[32][16];            // 32 k x 64 cols  (8 KB)
    int t  = threadIdx.x;
    int tx = t & 15;                          // col group: cols tx*4 .. tx*4+3
    int ty = t >> 4;                          // row group: rows ty*4 .. ty*4+3
    int row0 = blockIdx.x * 64;

    // acc[r][pair]: pair 0 = cols (0,1), pair 1 = cols (2,3) of this thread's 4 cols
    unsigned long long accA0 = pk2(0.f, 0.f), accB0 = pk2(0.f, 0.f);
    unsigned long long accA1 = pk2(0.f, 0.f), accB1 = pk2(0.f, 0.f);
    unsigned long long accA2 = pk2(0.f, 0.f), accB2 = pk2(0.f, 0.f);
    unsigned long long accA3 = pk2(0.f, 0.f), accB3 = pk2(0.f, 0.f);

    const float4* xg = (const float4*)x;      // x rows: 32 float4 each
    const float4* wg = (const float4*)W1;     // W1 rows: 16 float4 each

#pragma unroll
    for (int kc = 0; kc < 4; ++kc) {
        // load x chunk: 64 rows x 8 float4
        for (int i = t; i < 512; i += 256) {
            int row = i >> 3, k4 = i & 7;
            float4 v = make_float4(0.f, 0.f, 0.f, 0.f);
            if (row0 + row < N_NODES)
                v = xg[(size_t)(row0 + row) * 32 + kc * 8 + k4];
            xs4[row][k4] = v;
        }
        // load W chunk: 32 k x 16 float4 (contiguous rows of W1)
        for (int i = t; i < 512; i += 256) {
            int k = i >> 4, c4 = i & 15;
            ws4[k][c4] = wg[(size_t)(kc * 32 + k) * 16 + c4];
        }
        __syncthreads();

#pragma unroll
        for (int k4 = 0; k4 < 8; ++k4) {
            float4 a0 = xs4[ty * 4 + 0][k4];
            float4 a1 = xs4[ty * 4 + 1][k4];
            float4 a2 = xs4[ty * 4 + 2][k4];
            float4 a3 = xs4[ty * 4 + 3][k4];
#pragma unroll
            for (int kk = 0; kk < 4; ++kk) {
                float4 wv = ws4[k4 * 4 + kk][tx];
                unsigned long long w01 = pk2(wv.x, wv.y);
                unsigned long long w23 = pk2(wv.z, wv.w);
                float s0 = (kk == 0) ? a0.x : (kk == 1) ? a0.y : (kk == 2) ? a0.z : a0.w;
                float s1 = (kk == 0) ? a1.x : (kk == 1) ? a1.y : (kk == 2) ? a1.z : a1.w;
                float s2 = (kk == 0) ? a2.x : (kk == 1) ? a2.y : (kk == 2) ? a2.z : a2.w;
                float s3 = (kk == 0) ? a3.x : (kk == 1) ? a3.y : (kk == 2) ? a3.z : a3.w;
                unsigned long long d0 = pk2(s0, s0);
                unsigned long long d1 = pk2(s1, s1);
                unsigned long long d2 = pk2(s2, s2);
                unsigned long long d3 = pk2(s3, s3);
                fma2(accA0, d0, w01); fma2(accB0, d0, w23);
                fma2(accA1, d1, w01); fma2(accB1, d1, w23);
                fma2(accA2, d2, w01); fma2(accB2, d2, w23);
                fma2(accA3, d3, w01); fma2(accB3, d3, w23);
            }
        }
        __syncthreads();
    }

    // epilogue: unpack, scale by dinv[row], vector store
    int r = row0 + ty * 4;
    float4* yo = (float4*)g_y1;
    float4 o;
    if (r + 0 < N_NODES) {
        float d = g_dinv[r + 0];
        upk2(accA0, o.x, o.y); upk2(accB0, o.z, o.w);
        o.x *= d; o.y *= d; o.z *= d; o.w *= d;
        yo[(size_t)(r + 0) * 16 + tx] = o;
    }
    if (r + 1 < N_NODES) {
        float d = g_dinv[r + 1];
        upk2(accA1, o.x, o.y); upk2(accB1, o.z, o.w);
        o.x *= d; o.y *= d; o.z *= d; o.w *= d;
        yo[(size_t)(r + 1) * 16 + tx] = o;
    }
    if (r + 2 < N_NODES) {
        float d = g_dinv[r + 2];
        upk2(accA2, o.x, o.y); upk2(accB2, o.z, o.w);
        o.x *= d; o.y *= d; o.z *= d; o.w *= d;
        yo[(size_t)(r + 2) * 16 + tx] = o;
    }
    if (r + 3 < N_NODES) {
        float d = g_dinv[r + 3];
        upk2(accA3, o.x, o.y); upk2(accB3, o.z, o.w);
        o.x *= d; o.y *= d; o.z *= d; o.w *= d;
        yo[(size_t)(r + 3) * 16 + tx] = o;
    }
}

// ------- fused gather1 + GEMM2 -------
// Phase A (256 thr, 16 thr/node): h = relu( dinv·(Σ_nbr y1[nbr] + y1[d]) + b1 ) -> smem
// Phase B (192 thr): y2[16 rows, 48 cols] = (h @ W2pad) * dinv[row], written direct.
__global__ void k_g1g2(const float* __restrict__ b1, const float* __restrict__ W2) {
    __shared__ float hs[16][F_HID];           // 4 KB
    __shared__ float ws[F_HID][F_OUT_P];      // 12 KB (col 47 zero-padded)
    int t = threadIdx.x;
    for (int i = t; i < F_HID * F_OUT_P; i += 256) {
        int k = i / F_OUT_P, c = i - k * F_OUT_P;
        ws[k][c] = (c < F_OUT) ? W2[k * F_OUT + c] : 0.0f;
    }

    // ---- Phase A: gather ----
    int node = blockIdx.x * 16 + (t >> 4);
    int c = t & 15;
    const float4* y = (const float4*)g_y1;
    float di = g_dinv[node];
    float4 a0 = __ldg(&y[(size_t)node * 16 + c]);   // self term (unscaled!)
    float4 a1 = make_float4(0.f, 0.f, 0.f, 0.f);
    float4 a2 = make_float4(0.f, 0.f, 0.f, 0.f);
    float4 a3 = make_float4(0.f, 0.f, 0.f, 0.f);
    int j   = g_start[node];
    int end = j + g_cnt[node];
    for (; j + 4 <= end; j += 4) {                   // MLP=4
        int s0 = g_col[j + 0], s1 = g_col[j + 1];
        int s2 = g_col[j + 2], s3 = g_col[j + 3];
        float4 v0 = __ldg(&y[(size_t)s0 * 16 + c]);
        float4 v1 = __ldg(&y[(size_t)s1 * 16 + c]);
        float4 v2 = __ldg(&y[(size_t)s2 * 16 + c]);
        float4 v3 = __ldg(&y[(size_t)s3 * 16 + c]);
        a0.x += v0.x; a0.y += v0.y; a0.z += v0.z; a0.w += v0.w;
        a1.x += v1.x; a1.y += v1.y; a1.z += v1.z; a1.w += v1.w;
        a2.x += v2.x; a2.y += v2.y; a2.z += v2.z; a2.w += v2.w;
        a3.x += v3.x; a3.y += v3.y; a3.z += v3.z; a3.w += v3.w;
    }
    for (; j < end; ++j) {
        int s = g_col[j];
        float4 v = __ldg(&y[(size_t)s * 16 + c]);
        a0.x += v.x; a0.y += v.y; a0.z += v.z; a0.w += v.w;
    }
    a0.x += a1.x + a2.x + a3.x;
    a0.y += a1.y + a2.y + a3.y;
    a0.z += a1.z + a2.z + a3.z;
    a0.w += a1.w + a2.w + a3.w;
    float4 b = ((const float4*)b1)[c];
    float4 h;
    h.x = fmaxf(fmaf(a0.x, di, b.x), 0.f);
    h.y = fmaxf(fmaf(a0.y, di, b.y), 0.f);
    h.z = fmaxf(fmaf(a0.z, di, b.z), 0.f);
    h.w = fmaxf(fmaf(a0.w, di, b.w), 0.f);
    *(float4*)&hs[t >> 4][c * 4] = h;
    __syncthreads();

    // ---- Phase B: 16x48 = h[16x64] @ ws[64x48] ----
    if (t < 192) {
        int cp = t % 24;
        int rg = t / 24;                       // 0..7
        int c0 = cp * 2;
        float acc00 = 0.f, acc01 = 0.f, acc10 = 0.f, acc11 = 0.f;
#pragma unroll 8
        for (int k = 0; k < F_HID; ++k) {
            float va = hs[rg * 2 + 0][k];
            float vb = hs[rg * 2 + 1][k];
            float w0 = ws[k][c0];
            float w1 = ws[k][c0 + 1];
            acc00 += va * w0; acc01 += va * w1;
            acc10 += vb * w0; acc11 += vb * w1;
        }
        int r0 = blockIdx.x * 16 + rg * 2;
        float d0 = g_dinv[r0 + 0];
        float d1 = g_dinv[r0 + 1];
        g_y2[(size_t)(r0 + 0) * F_OUT_P + c0 + 0] = acc00 * d0;
        g_y2[(size_t)(r0 + 0) * F_OUT_P + c0 + 1] = acc01 * d0;
        g_y2[(size_t)(r0 + 1) * F_OUT_P + c0 + 0] = acc10 * d1;
        g_y2[(size_t)(r0 + 1) * F_OUT_P + c0 + 1] = acc11 * d1;
    }
}

// ------- gather2 + fused log-softmax: out = logsoftmax( dinv·(Σ + y2[d]) + b2 ) -------
__global__ void k_gather2(const float* __restrict__ b2, float* __restrict__ out) {
    int t = threadIdx.x;
    int node = blockIdx.x * 16 + (t >> 4);
    int c = t & 15;
    bool act = (c < 12);
    float di = g_dinv[node];
    float4 v = make_float4(-1e30f, -1e30f, -1e30f, -1e30f);

    if (act) {
        const float4* y = (const float4*)g_y2;
        float4 a0 = __ldg(&y[(size_t)node * 12 + c]);   // self term (unscaled)
        float4 a1 = make_float4(0.f, 0.f, 0.f, 0.f);
        float4 a2 = make_float4(0.f, 0.f, 0.f, 0.f);
        float4 a3 = make_float4(0.f, 0.f, 0.f, 0.f);
        int j   = g_start[node];
        int end = j + g_cnt[node];
        for (; j + 4 <= end; j += 4) {                   // MLP=4
            int s0 = g_col[j + 0], s1 = g_col[j + 1];
            int s2 = g_col[j + 2], s3 = g_col[j + 3];
            float4 v0 = __ldg(&y[(size_t)s0 * 12 + c]);
            float4 v1 = __ldg(&y[(size_t)s1 * 12 + c]);
            float4 v2 = __ldg(&y[(size_t)s2 * 12 + c]);
            float4 v3 = __ldg(&y[(size_t)s3 * 12 + c]);
            a0.x += v0.x; a0.y += v0.y; a0.z += v0.z; a0.w += v0.w;
            a1.x += v1.x; a1.y += v1.y; a1.z += v1.z; a1.w += v1.w;
            a2.x += v2.x; a2.y += v2.y; a2.z += v2.z; a2.w += v2.w;
            a3.x += v3.x; a3.y += v3.y; a3.z += v3.z; a3.w += v3.w;
        }
        for (; j < end; ++j) {
            int s = g_col[j];
            float4 w = __ldg(&y[(size_t)s * 12 + c]);
            a0.x += w.x; a0.y += w.y; a0.z += w.z; a0.w += w.w;
        }
        a0.x += a1.x + a2.x + a3.x;
        a0.y += a1.y + a2.y + a3.y;
        a0.z += a1.z + a2.z + a3.z;
        a0.w += a1.w + a2.w + a3.w;

        float bx, by, bz, bw;
        if (c < 11) {
            bx = b2[c * 4 + 0]; by = b2[c * 4 + 1];
            bz = b2[c * 4 + 2]; bw = b2[c * 4 + 3];
        } else {
            bx = b2[44]; by = b2[45]; bz = b2[46]; bw = 0.f;
        }
        v.x = fmaf(a0.x, di, bx);
        v.y = fmaf(a0.y, di, by);
        v.z = fmaf(a0.z, di, bz);
        v.w = (c < 11) ? fmaf(a0.w, di, bw) : -1e30f;   // col 47 is padding
    }

    float m = fmaxf(fmaxf(v.x, v.y), fmaxf(v.z, v.w));
#pragma unroll
    for (int off = 1; off < 16; off <<= 1)
        m = fmaxf(m, __shfl_xor_sync(0xffffffffu, m, off, 16));

    float s = act ? (expf(v.x - m) + expf(v.y - m) + expf(v.z - m) + expf(v.w - m))
                  : 0.f;
#pragma unroll
    for (int off = 1; off < 16; off <<= 1)
        s += __shfl_xor_sync(0xffffffffu, s, off, 16);

    float ls = m + logf(s);
    if (act) {
        size_t base = (size_t)node * F_OUT + c * 4;
        out[base + 0] = v.x - ls;
        out[base + 1] = v.y - ls;
        out[base + 2] = v.z - ls;
        if (c < 11) out[base + 3] = v.w - ls;
    }
}

// ---------------- launch (6 kernels + 2 memset nodes, graph-capturable) ----------------
extern "C" void kernel_launch(void* const* d_in, const int* in_sizes, int n_in,
                              void* d_out, int out_size) {
    const float* x  = (const float*)d_in[0];
    const int*   ei = (const int*)  d_in[1];
    const float* W1 = (const float*)d_in[2];
    const float* b1 = (const float*)d_in[3];
    const float* W2 = (const float*)d_in[4];
    const float* b2 = (const float*)d_in[5];
    float* out = (float*)d_out;
    const int* src = ei;
    const int* dst = ei + N_EDGES;

    void *p_cnt = nullptr, *p_alloc = nullptr;
    cudaGetSymbolAddress(&p_cnt,   g_cnt);
    cudaGetSymbolAddress(&p_alloc, g_alloc);
    cudaMemsetAsync(p_cnt,   0, N_NODES * sizeof(int));
    cudaMemsetAsync(p_alloc, 0, sizeof(int));

    // CSR build
    k_cnt     <<<(N_EDGES + 255) / 256, 256>>>(dst);
    k_scanfix <<<NBLK_N, 256>>>();
    k_fill    <<<(N_EDGES + 255) / 256, 256>>>(src, dst);

    // layer 1 GEMM (FFMA2 register-blocked), fused gather1+GEMM2, fused gather2+softmax
    k_gemm1   <<<(N_NODES + 63) / 64, 256>>>(x, W1);
    k_g1g2    <<<N_NODES / 16, 256>>>(b1, W2);
    k_gather2 <<<N_NODES / 16, 256>>>(b2, out);
}